// round 10
// baseline (speedup 1.0000x reference)
#include <cuda_runtime.h>
#include <cuda_fp16.h>
#include <cstdint>

// Problem: B=2, H=16, S=2048, D=128, fp32 in/out, int32 mask over keys.
// Masked keys (~50%) contribute exactly zero -> K/V compacted in prep.
// Padding slots are ZERO rows: p = 2^0 = 1 exactly, contributes 0 to O;
// exact pad count subtracted from l in the epilogue.
// fp16, m16n8k16, 32 q-rows/warp. This round: half-tile phase interleave
// (S0 / exp0 / S1 / PV0 / exp1 / PV1) so the 2 warps/SMSP run in antiphase,
// exp2f with log2e folded into Q scaling, 4-stage cp.async pipeline.
constexpr int Bc = 2, Hh = 16, Ss = 2048, Dd = 128;
constexpr int BM = 128;         // queries per block (4 warps x 32 rows)
constexpr int BN = 32;          // keys per tile
constexpr int NT = 128;         // threads
constexpr float QSCALE = 0.08838834764831845f * 1.4426950408889634f; // /sqrt(128)*log2(e)

constexpr int KTILEB = 32 * 256;    // 8192  (32 keys x 128 fp16, XOR-swizzled rows)
constexpr int VROWB = 80;           // 32 fp16 = 64B + 16B pad
constexpr int VTILEB = 128 * VROWB; // 10240
constexpr int NSTAGE = 4;

// fp16 operands, compacted: g_kh [bh][j][d], g_vth [bh][d][j] (zeros at padding)
__device__ __align__(16) __half g_kh[(size_t)Bc * Hh * Ss * Dd];
__device__ __align__(16) __half g_vth[(size_t)Bc * Hh * Dd * Ss];

__device__ __forceinline__ uint32_t f2h2(float lo, float hi) {
    __half2 h = __floats2half2_rn(lo, hi);
    return *(uint32_t*)&h;
}

__device__ __forceinline__ void mma16(float* d, uint32_t a0, uint32_t a1, uint32_t a2,
                                      uint32_t a3, uint32_t b0, uint32_t b1) {
    asm volatile(
        "mma.sync.aligned.m16n8k16.row.col.f32.f16.f16.f32 "
        "{%0,%1,%2,%3},{%4,%5,%6,%7},{%8,%9},{%0,%1,%2,%3};"
        : "+f"(d[0]), "+f"(d[1]), "+f"(d[2]), "+f"(d[3])
        : "r"(a0), "r"(a1), "r"(a2), "r"(a3), "r"(b0), "r"(b1));
}

__device__ __forceinline__ void ldsm4(uint32_t& t0, uint32_t& t1, uint32_t& t2,
                                      uint32_t& t3, uint32_t addr) {
    asm volatile("ldmatrix.sync.aligned.m8n8.x4.shared.b16 {%0,%1,%2,%3}, [%4];"
                 : "=r"(t0), "=r"(t1), "=r"(t2), "=r"(t3) : "r"(addr));
}

__device__ __forceinline__ void cp16(uint32_t dst, const void* src) {
    asm volatile("cp.async.ca.shared.global [%0], [%1], 16;" :: "r"(dst), "l"(src));
}
#define CP_COMMIT() asm volatile("cp.async.commit_group;" ::: "memory")

// ---------------- prep: scan (recomputed per block) + gather + fp16 convert ----
__global__ void __launch_bounds__(256) prep_kernel(const float* __restrict__ k,
                                                   const float* __restrict__ v,
                                                   const int* __restrict__ mask) {
    __shared__ float sv[64 * 129];
    __shared__ int wcnt[64], woff[64];
    __shared__ int sidx[64];
    __shared__ int s_ntrue;
    const int t = blockIdx.x, bh = blockIdx.y, tid = threadIdx.x;
    const int b = bh >> 4;
    const int warp = tid >> 5, lane = tid & 31;

    for (int ch = warp; ch < 64; ch += 8) {
        int m = mask[b * Ss + ch * 32 + lane] != 0;
        unsigned bal = __ballot_sync(0xffffffffu, m);
        if (lane == 0) wcnt[ch] = __popc(bal);
    }
    __syncthreads();
    if (tid == 0) {
        int s = 0;
        for (int i = 0; i < 64; i++) { woff[i] = s; s += wcnt[i]; }
        s_ntrue = s;
    }
    __syncthreads();
    const int ntrue = s_ntrue;
    const int npad = (ntrue + 63) & ~63;
    if (t * 64 >= npad) return;
    const int base = t * 64;

    if (tid < 64) sidx[tid] = -1;   // -1 => zero padding row
    __syncthreads();
    for (int ch = warp; ch < 64; ch += 8) {
        int src = ch * 32 + lane;
        int m = mask[b * Ss + src] != 0;
        unsigned bal = __ballot_sync(0xffffffffu, m);
        if (m) {
            int pos = woff[ch] + __popc(bal & ((1u << lane) - 1u));
            if (pos >= base && pos < base + 64) sidx[pos - base] = src;
        }
    }
    __syncthreads();

    const float* kg = k + (size_t)bh * Ss * Dd;
    const float* vg = v + (size_t)bh * Ss * Dd;

    uint32_t* ko = (uint32_t*)(g_kh + ((size_t)bh * Ss + base) * Dd);
    for (int i = tid; i < 64 * 32; i += 256) {
        int r = i >> 5, c4 = (i & 31) << 2;
        int idx = sidx[r];
        float4 x = (idx >= 0) ? *(const float4*)(kg + (size_t)idx * Dd + c4)
                              : make_float4(0.f, 0.f, 0.f, 0.f);
        ko[(r * Dd + c4) >> 1] = f2h2(x.x, x.y);
        ko[((r * Dd + c4) >> 1) + 1] = f2h2(x.z, x.w);
    }

    for (int i = tid; i < 64 * 32; i += 256) {
        int r = i >> 5, c4 = (i & 31) << 2;
        int idx = sidx[r];
        float4 x = (idx >= 0) ? *(const float4*)(vg + (size_t)idx * Dd + c4)
                              : make_float4(0.f, 0.f, 0.f, 0.f);
        sv[r * 129 + c4 + 0] = x.x; sv[r * 129 + c4 + 1] = x.y;
        sv[r * 129 + c4 + 2] = x.z; sv[r * 129 + c4 + 3] = x.w;
    }
    __syncthreads();
    uint32_t* vo = (uint32_t*)(g_vth + (size_t)bh * Dd * Ss);
    for (int i = tid; i < 128 * 32; i += 256) {
        int d = i >> 5, kp = i & 31;
        uint32_t h = f2h2(sv[(2 * kp) * 129 + d], sv[(2 * kp + 1) * 129 + d]);
        vo[((size_t)d * Ss + base) / 2 + kp] = h;
    }
}

// ---------------- main kernel ----------------
// dyn smem: 4 x (K 8192 + V 10240) = 73728 B -> 2 CTAs/SM (reg-limited)
__global__ void __launch_bounds__(NT, 2)
fa_kernel(const float* __restrict__ q, const int* __restrict__ mask,
          float* __restrict__ out) {
    extern __shared__ char sm[];
    __shared__ int red[4];
    const uint32_t sbase = (uint32_t)__cvta_generic_to_shared(sm);
    uint32_t Kaddr[NSTAGE], Vaddr[NSTAGE];
#pragma unroll
    for (int i = 0; i < NSTAGE; i++) {
        Kaddr[i] = sbase + i * KTILEB;
        Vaddr[i] = sbase + NSTAGE * KTILEB + i * VTILEB;
    }

    const int tid = threadIdx.x, warp = tid >> 5, lane = tid & 31;
    const int g = lane >> 2, tig = lane & 3;
    const int qb = blockIdx.x, bh = blockIdx.y, b = bh >> 4;  // Hh=16
    const size_t bh_base = (size_t)bh * Ss * Dd;

    // count unmasked keys (mask is 8KB, L2-hot)
    int cnt = 0;
    for (int i = tid; i < Ss; i += NT) cnt += (mask[b * Ss + i] != 0);
#pragma unroll
    for (int s = 16; s > 0; s >>= 1) cnt += __shfl_xor_sync(0xffffffffu, cnt, s);
    if (lane == 0) red[warp] = cnt;
    __syncthreads();
    const int ntrue = red[0] + red[1] + red[2] + red[3];
    const int ntiles = (ntrue + BN - 1) >> 5;
    const float padf = (float)(ntiles * BN - ntrue);

    // Q fragments straight from global, pre-scaled by 1/sqrt(d)*log2(e)
    const float* qg = q + bh_base + (size_t)qb * BM * Dd;
    const int rA = warp * 32 + g;               // block0 rows rA, rA+8
    uint32_t qf[8][2][4];
#pragma unroll
    for (int kk = 0; kk < 8; kk++) {
#pragma unroll
        for (int h = 0; h < 2; h++) {
            const float* p0 = qg + (size_t)(rA + 16 * h) * Dd + kk * 16 + 2 * tig;
            const float* p1 = p0 + 8 * Dd;
            float2 a = *(const float2*)(p0);
            float2 bq = *(const float2*)(p1);
            float2 c = *(const float2*)(p0 + 8);
            float2 d = *(const float2*)(p1 + 8);
            qf[kk][h][0] = f2h2(a.x * QSCALE, a.y * QSCALE);
            qf[kk][h][1] = f2h2(bq.x * QSCALE, bq.y * QSCALE);
            qf[kk][h][2] = f2h2(c.x * QSCALE, c.y * QSCALE);
            qf[kk][h][3] = f2h2(d.x * QSCALE, d.y * QSCALE);
        }
    }

    const __half* ksrc = g_kh + (size_t)bh * Ss * Dd;
    const __half* vsrc = g_vth + (size_t)bh * Dd * Ss;

    auto issue_tile = [&](int t, int bi) {
        const __half* ks = ksrc + (size_t)t * BN * Dd;
#pragma unroll
        for (int i = 0; i < 4; i++) {          // K: 32 rows x 16 chunks of 16B
            int ch = tid + i * NT;
            int r = ch >> 4, c = ch & 15;
            cp16(Kaddr[bi] + r * 256 + ((c ^ (r & 7)) << 4), ks + r * Dd + c * 8);
        }
        const __half* vs = vsrc + (size_t)t * BN;
#pragma unroll
        for (int i = 0; i < 4; i++) {          // VT: 128 rows x 4 chunks of 16B
            int ch = tid + i * NT;
            int r = ch >> 2, c = ch & 3;
            cp16(Vaddr[bi] + r * VROWB + c * 16, vs + (size_t)r * Ss + c * 8);
        }
        CP_COMMIT();
    };

    // ldmatrix lane addressing (x4)
    const int mi = lane >> 3, mrow = lane & 7;
    const uint32_t krow = (uint32_t)((8 * (mi >> 1) + mrow) * 256);
    const uint32_t vrow = (uint32_t)((8 * (mi >> 1) + mrow) * VROWB);
    const int cbase = mi & 1;

    float oa[2][16][4];
#pragma unroll
    for (int h = 0; h < 2; h++)
#pragma unroll
        for (int n = 0; n < 16; n++)
            oa[h][n][0] = oa[h][n][1] = oa[h][n][2] = oa[h][n][3] = 0.f;
    float l00 = 0.f, l01 = 0.f, l10 = 0.f, l11 = 0.f;

    issue_tile(0, 0);
    if (1 < ntiles) issue_tile(1, 1);
    if (2 < ntiles) issue_tile(2, 2);

#pragma unroll 1
    for (int t = 0; t < ntiles; t++) {
        const int bi = t & (NSTAGE - 1);
        if (t + 3 <= ntiles - 1)
            asm volatile("cp.async.wait_group 2;" ::: "memory");
        else if (t + 2 <= ntiles - 1)
            asm volatile("cp.async.wait_group 1;" ::: "memory");
        else
            asm volatile("cp.async.wait_group 0;" ::: "memory");
        __syncthreads();             // tile t visible; all warps done with t-1
        if (t + 3 < ntiles) issue_tile(t + 3, (t + 3) & (NSTAGE - 1));

        const uint32_t kb = Kaddr[bi] + krow;
        const uint32_t vb = Vaddr[bi] + vrow;
        float sa[2][4][4];
        uint32_t ph0[2][4], ph1[2][4];

        // ---- S phase 0: columns 0..15 (jp=0) ----
#pragma unroll
        for (int h = 0; h < 2; h++)
#pragma unroll
            for (int j = 0; j < 2; j++)
                sa[h][j][0] = sa[h][j][1] = sa[h][j][2] = sa[h][j][3] = 0.f;
#pragma unroll
        for (int kk = 0; kk < 8; kk++) {
            uint32_t t0, t1, t2, t3;
            ldsm4(t0, t1, t2, t3, kb + (uint32_t)(((kk * 2 + cbase) ^ mrow) << 4));
            mma16(sa[0][0], qf[kk][0][0], qf[kk][0][1], qf[kk][0][2], qf[kk][0][3], t0, t1);
            mma16(sa[0][1], qf[kk][0][0], qf[kk][0][1], qf[kk][0][2], qf[kk][0][3], t2, t3);
            mma16(sa[1][0], qf[kk][1][0], qf[kk][1][1], qf[kk][1][2], qf[kk][1][3], t0, t1);
            mma16(sa[1][1], qf[kk][1][0], qf[kk][1][1], qf[kk][1][2], qf[kk][1][3], t2, t3);
        }

        // ---- exp phase 0 (cols 0..15): p = 2^s ----
#pragma unroll
        for (int hj = 0; hj < 4; hj++) {
            const int h = hj >> 1, j = hj & 1;
            float p0 = exp2f(sa[h][j][0]);
            float p1 = exp2f(sa[h][j][1]);
            float p2 = exp2f(sa[h][j][2]);
            float p3 = exp2f(sa[h][j][3]);
            if (h == 0) { l00 += p0 + p1; l01 += p2 + p3; }
            else        { l10 += p0 + p1; l11 += p2 + p3; }
            ph0[h][j] = f2h2(p0, p1);
            ph1[h][j] = f2h2(p2, p3);
        }

        // ---- S phase 1: columns 16..31 (jp=1) — overlaps exp0's MUFU shadow ----
#pragma unroll
        for (int h = 0; h < 2; h++)
#pragma unroll
            for (int j = 2; j < 4; j++)
                sa[h][j][0] = sa[h][j][1] = sa[h][j][2] = sa[h][j][3] = 0.f;
#pragma unroll
        for (int kk = 0; kk < 8; kk++) {
            uint32_t t0, t1, t2, t3;
            ldsm4(t0, t1, t2, t3,
                  kb + 4096u + (uint32_t)(((kk * 2 + cbase) ^ mrow) << 4));
            mma16(sa[0][2], qf[kk][0][0], qf[kk][0][1], qf[kk][0][2], qf[kk][0][3], t0, t1);
            mma16(sa[0][3], qf[kk][0][0], qf[kk][0][1], qf[kk][0][2], qf[kk][0][3], t2, t3);
            mma16(sa[1][2], qf[kk][1][0], qf[kk][1][1], qf[kk][1][2], qf[kk][1][3], t0, t1);
            mma16(sa[1][3], qf[kk][1][0], qf[kk][1][1], qf[kk][1][2], qf[kk][1][3], t2, t3);
        }

        // ---- PV phase 0: key chunk 0..15 (uses exp0 outputs) ----
        {
            const uint32_t vch = (uint32_t)(cbase << 4);
            uint32_t a0 = ph0[0][0], a1 = ph1[0][0], a2 = ph0[0][1], a3 = ph1[0][1];
            uint32_t b0 = ph0[1][0], b1 = ph1[1][0], b2 = ph0[1][1], b3 = ph1[1][1];
#pragma unroll
            for (int np = 0; np < 8; np++) {
                uint32_t t0, t1, t2, t3;
                ldsm4(t0, t1, t2, t3, vb + np * (16 * VROWB) + vch);
                mma16(oa[0][2 * np], a0, a1, a2, a3, t0, t1);
                mma16(oa[0][2 * np + 1], a0, a1, a2, a3, t2, t3);
                mma16(oa[1][2 * np], b0, b1, b2, b3, t0, t1);
                mma16(oa[1][2 * np + 1], b0, b1, b2, b3, t2, t3);
            }
        }

        // ---- exp phase 1 (cols 16..31) — overlaps PV0's tensor shadow ----
#pragma unroll
        for (int hj = 0; hj < 4; hj++) {
            const int h = hj >> 1, j = 2 + (hj & 1);
            float p0 = exp2f(sa[h][j][0]);
            float p1 = exp2f(sa[h][j][1]);
            float p2 = exp2f(sa[h][j][2]);
            float p3 = exp2f(sa[h][j][3]);
            if (h == 0) { l00 += p0 + p1; l01 += p2 + p3; }
            else        { l10 += p0 + p1; l11 += p2 + p3; }
            ph0[h][j] = f2h2(p0, p1);
            ph1[h][j] = f2h2(p2, p3);
        }

        // ---- PV phase 1: key chunk 16..31 ----
        {
            const uint32_t vch = (uint32_t)((2 + cbase) << 4);
            uint32_t a0 = ph0[0][2], a1 = ph1[0][2], a2 = ph0[0][3], a3 = ph1[0][3];
            uint32_t b0 = ph0[1][2], b1 = ph1[1][2], b2 = ph0[1][3], b3 = ph1[1][3];
#pragma unroll
            for (int np = 0; np < 8; np++) {
                uint32_t t0, t1, t2, t3;
                ldsm4(t0, t1, t2, t3, vb + np * (16 * VROWB) + vch);
                mma16(oa[0][2 * np], a0, a1, a2, a3, t0, t1);
                mma16(oa[0][2 * np + 1], a0, a1, a2, a3, t2, t3);
                mma16(oa[1][2 * np], b0, b1, b2, b3, t0, t1);
                mma16(oa[1][2 * np + 1], b0, b1, b2, b3, t2, t3);
            }
        }
    }

    // ---- epilogue: quad-reduce l, subtract exact padding count, store ----
    l00 += __shfl_xor_sync(0xffffffffu, l00, 1);
    l00 += __shfl_xor_sync(0xffffffffu, l00, 2);
    l01 += __shfl_xor_sync(0xffffffffu, l01, 1);
    l01 += __shfl_xor_sync(0xffffffffu, l01, 2);
    l10 += __shfl_xor_sync(0xffffffffu, l10, 1);
    l10 += __shfl_xor_sync(0xffffffffu, l10, 2);
    l11 += __shfl_xor_sync(0xffffffffu, l11, 1);
    l11 += __shfl_xor_sync(0xffffffffu, l11, 2);
    const float inv[2][2] = {{1.f / (l00 - padf), 1.f / (l01 - padf)},
                             {1.f / (l10 - padf), 1.f / (l11 - padf)}};
    float* og = out + bh_base + (size_t)qb * BM * Dd;
#pragma unroll
    for (int h = 0; h < 2; h++) {
        const int ra = rA + 16 * h, rb = ra + 8;
#pragma unroll
        for (int n = 0; n < 16; n++) {
            int c = n * 8 + 2 * tig;
            *(float2*)(og + (size_t)ra * Dd + c) =
                make_float2(oa[h][n][0] * inv[h][0], oa[h][n][1] * inv[h][0]);
            *(float2*)(og + (size_t)rb * Dd + c) =
                make_float2(oa[h][n][2] * inv[h][1], oa[h][n][3] * inv[h][1]);
        }
    }
}

extern "C" void kernel_launch(void* const* d_in, const int* in_sizes, int n_in,
                              void* d_out, int out_size) {
    (void)in_sizes; (void)n_in; (void)out_size;
    const float* q = (const float*)d_in[0];
    const float* k = (const float*)d_in[1];
    const float* v = (const float*)d_in[2];
    const int* mask = (const int*)d_in[3];
    float* out = (float*)d_out;

    prep_kernel<<<dim3(Ss / 64, Bc * Hh), 256>>>(k, v, mask);

    constexpr int SMEM_BYTES = NSTAGE * (KTILEB + VTILEB);  // 73728
    cudaFuncSetAttribute(fa_kernel, cudaFuncAttributeMaxDynamicSharedMemorySize,
                         SMEM_BYTES);
    fa_kernel<<<dim3(Ss / BM, Bc * Hh), NT, SMEM_BYTES>>>(q, mask, out);
}

// round 11
// speedup vs baseline: 1.0509x; 1.0509x over previous
#include <cuda_runtime.h>
#include <cuda_fp16.h>
#include <cstdint>

// Problem: B=2, H=16, S=2048, D=128, fp32 in/out, int32 mask over keys.
// Masked keys (~50%) contribute exactly zero -> K/V compacted in prep.
// Padding slots are ZERO rows: p = 2^0 = 1 exactly, contributes 0 to O;
// exact pad count subtracted from l in the epilogue.
// fp16, m16n8k16, 32 q-rows/warp (ldsm amortized over 4 MMAs).
// This round: Q fragments live in swizzled SMEM and are re-loaded per tile
// via ldmatrix (frees 64 registers -> no spills, scheduling slack), simple
// phase order, 4-stage cp.async pipeline.
constexpr int Bc = 2, Hh = 16, Ss = 2048, Dd = 128;
constexpr int BM = 128;         // queries per block (4 warps x 32 rows)
constexpr int BN = 32;          // keys per tile
constexpr int NT = 128;         // threads
constexpr float QSCALE = 0.08838834764831845f * 1.4426950408889634f; // /sqrt(128)*log2(e)

constexpr int QTILEB = 128 * 256;   // 32768 (128 q-rows x 128 fp16, XOR-swizzled)
constexpr int KTILEB = 32 * 256;    // 8192  (32 keys x 128 fp16, XOR-swizzled rows)
constexpr int VROWB = 80;           // 32 fp16 = 64B + 16B pad
constexpr int VTILEB = 128 * VROWB; // 10240
constexpr int NSTAGE = 4;

// fp16 operands, compacted: g_kh [bh][j][d], g_vth [bh][d][j] (zeros at padding)
__device__ __align__(16) __half g_kh[(size_t)Bc * Hh * Ss * Dd];
__device__ __align__(16) __half g_vth[(size_t)Bc * Hh * Dd * Ss];

__device__ __forceinline__ uint32_t f2h2(float lo, float hi) {
    __half2 h = __floats2half2_rn(lo, hi);
    return *(uint32_t*)&h;
}

__device__ __forceinline__ void mma16(float* d, uint32_t a0, uint32_t a1, uint32_t a2,
                                      uint32_t a3, uint32_t b0, uint32_t b1) {
    asm volatile(
        "mma.sync.aligned.m16n8k16.row.col.f32.f16.f16.f32 "
        "{%0,%1,%2,%3},{%4,%5,%6,%7},{%8,%9},{%0,%1,%2,%3};"
        : "+f"(d[0]), "+f"(d[1]), "+f"(d[2]), "+f"(d[3])
        : "r"(a0), "r"(a1), "r"(a2), "r"(a3), "r"(b0), "r"(b1));
}

__device__ __forceinline__ void ldsm4(uint32_t& t0, uint32_t& t1, uint32_t& t2,
                                      uint32_t& t3, uint32_t addr) {
    asm volatile("ldmatrix.sync.aligned.m8n8.x4.shared.b16 {%0,%1,%2,%3}, [%4];"
                 : "=r"(t0), "=r"(t1), "=r"(t2), "=r"(t3) : "r"(addr));
}

__device__ __forceinline__ void cp16(uint32_t dst, const void* src) {
    asm volatile("cp.async.ca.shared.global [%0], [%1], 16;" :: "r"(dst), "l"(src));
}
__device__ __forceinline__ void sts128(uint32_t a, uint32_t x, uint32_t y,
                                       uint32_t z, uint32_t w) {
    asm volatile("st.shared.v4.b32 [%0], {%1,%2,%3,%4};"
                 :: "r"(a), "r"(x), "r"(y), "r"(z), "r"(w));
}
#define CP_COMMIT() asm volatile("cp.async.commit_group;" ::: "memory")

// ---------------- prep: scan (recomputed per block) + gather + fp16 convert ----
__global__ void __launch_bounds__(256) prep_kernel(const float* __restrict__ k,
                                                   const float* __restrict__ v,
                                                   const int* __restrict__ mask) {
    __shared__ float sv[64 * 129];
    __shared__ int wcnt[64], woff[64];
    __shared__ int sidx[64];
    __shared__ int s_ntrue;
    const int t = blockIdx.x, bh = blockIdx.y, tid = threadIdx.x;
    const int b = bh >> 4;
    const int warp = tid >> 5, lane = tid & 31;

    for (int ch = warp; ch < 64; ch += 8) {
        int m = mask[b * Ss + ch * 32 + lane] != 0;
        unsigned bal = __ballot_sync(0xffffffffu, m);
        if (lane == 0) wcnt[ch] = __popc(bal);
    }
    __syncthreads();
    if (tid == 0) {
        int s = 0;
        for (int i = 0; i < 64; i++) { woff[i] = s; s += wcnt[i]; }
        s_ntrue = s;
    }
    __syncthreads();
    const int ntrue = s_ntrue;
    const int npad = (ntrue + 63) & ~63;
    if (t * 64 >= npad) return;
    const int base = t * 64;

    if (tid < 64) sidx[tid] = -1;   // -1 => zero padding row
    __syncthreads();
    for (int ch = warp; ch < 64; ch += 8) {
        int src = ch * 32 + lane;
        int m = mask[b * Ss + src] != 0;
        unsigned bal = __ballot_sync(0xffffffffu, m);
        if (m) {
            int pos = woff[ch] + __popc(bal & ((1u << lane) - 1u));
            if (pos >= base && pos < base + 64) sidx[pos - base] = src;
        }
    }
    __syncthreads();

    const float* kg = k + (size_t)bh * Ss * Dd;
    const float* vg = v + (size_t)bh * Ss * Dd;

    uint32_t* ko = (uint32_t*)(g_kh + ((size_t)bh * Ss + base) * Dd);
    for (int i = tid; i < 64 * 32; i += 256) {
        int r = i >> 5, c4 = (i & 31) << 2;
        int idx = sidx[r];
        float4 x = (idx >= 0) ? *(const float4*)(kg + (size_t)idx * Dd + c4)
                              : make_float4(0.f, 0.f, 0.f, 0.f);
        ko[(r * Dd + c4) >> 1] = f2h2(x.x, x.y);
        ko[((r * Dd + c4) >> 1) + 1] = f2h2(x.z, x.w);
    }

    for (int i = tid; i < 64 * 32; i += 256) {
        int r = i >> 5, c4 = (i & 31) << 2;
        int idx = sidx[r];
        float4 x = (idx >= 0) ? *(const float4*)(vg + (size_t)idx * Dd + c4)
                              : make_float4(0.f, 0.f, 0.f, 0.f);
        sv[r * 129 + c4 + 0] = x.x; sv[r * 129 + c4 + 1] = x.y;
        sv[r * 129 + c4 + 2] = x.z; sv[r * 129 + c4 + 3] = x.w;
    }
    __syncthreads();
    uint32_t* vo = (uint32_t*)(g_vth + (size_t)bh * Dd * Ss);
    for (int i = tid; i < 128 * 32; i += 256) {
        int d = i >> 5, kp = i & 31;
        uint32_t h = f2h2(sv[(2 * kp) * 129 + d], sv[(2 * kp + 1) * 129 + d]);
        vo[((size_t)d * Ss + base) / 2 + kp] = h;
    }
}

// ---------------- main kernel ----------------
// dyn smem: Q 32768 + 4 x (K 8192 + V 10240) = 106496 B -> 2 CTAs/SM
__global__ void __launch_bounds__(NT, 2)
fa_kernel(const float* __restrict__ q, const int* __restrict__ mask,
          float* __restrict__ out) {
    extern __shared__ char sm[];
    __shared__ int red[4];
    const uint32_t sbase = (uint32_t)__cvta_generic_to_shared(sm);
    const uint32_t Qaddr = sbase;
    uint32_t Kaddr[NSTAGE], Vaddr[NSTAGE];
#pragma unroll
    for (int i = 0; i < NSTAGE; i++) {
        Kaddr[i] = sbase + QTILEB + i * KTILEB;
        Vaddr[i] = sbase + QTILEB + NSTAGE * KTILEB + i * VTILEB;
    }

    const int tid = threadIdx.x, warp = tid >> 5, lane = tid & 31;
    const int g = lane >> 2, tig = lane & 3;
    const int qb = blockIdx.x, bh = blockIdx.y, b = bh >> 4;  // Hh=16
    const size_t bh_base = (size_t)bh * Ss * Dd;

    const __half* ksrc = g_kh + (size_t)bh * Ss * Dd;
    const __half* vsrc = g_vth + (size_t)bh * Dd * Ss;

    auto issue_tile = [&](int t, int bi) {
        const __half* ks = ksrc + (size_t)t * BN * Dd;
#pragma unroll
        for (int i = 0; i < 4; i++) {          // K: 32 rows x 16 chunks of 16B
            int ch = tid + i * NT;
            int r = ch >> 4, c = ch & 15;
            cp16(Kaddr[bi] + r * 256 + ((c ^ (r & 7)) << 4), ks + r * Dd + c * 8);
        }
        const __half* vs = vsrc + (size_t)t * BN;
#pragma unroll
        for (int i = 0; i < 4; i++) {          // VT: 128 rows x 4 chunks of 16B
            int ch = tid + i * NT;
            int r = ch >> 2, c = ch & 3;
            cp16(Vaddr[bi] + r * VROWB + c * 16, vs + (size_t)r * Ss + c * 8);
        }
        CP_COMMIT();
    };

    // count unmasked keys (mask is 8KB, L2-hot)
    int cnt = 0;
    for (int i = tid; i < Ss; i += NT) cnt += (mask[b * Ss + i] != 0);
#pragma unroll
    for (int s = 16; s > 0; s >>= 1) cnt += __shfl_xor_sync(0xffffffffu, cnt, s);
    if (lane == 0) red[warp] = cnt;

    // get the first loads moving before staging Q
    issue_tile(0, 0);

    // stage Q into swizzled smem (pre-scaled fp16): 2048 chunks of 16B
    const float* qg = q + bh_base + (size_t)qb * BM * Dd;
#pragma unroll
    for (int i = 0; i < 16; i++) {
        int ch = tid + i * NT;
        int r = ch >> 4, c = ch & 15;
        const float* p = qg + (size_t)r * Dd + c * 8;
        float4 x = *(const float4*)(p);
        float4 y = *(const float4*)(p + 4);
        sts128(Qaddr + r * 256 + ((c ^ (r & 7)) << 4),
               f2h2(x.x * QSCALE, x.y * QSCALE), f2h2(x.z * QSCALE, x.w * QSCALE),
               f2h2(y.x * QSCALE, y.y * QSCALE), f2h2(y.z * QSCALE, y.w * QSCALE));
    }
    __syncthreads();   // Q + red visible
    const int ntrue = red[0] + red[1] + red[2] + red[3];
    const int ntiles = (ntrue + BN - 1) >> 5;
    const float padf = (float)(ntiles * BN - ntrue);

    if (1 < ntiles) issue_tile(1, 1);
    if (2 < ntiles) issue_tile(2, 2);

    // ldmatrix lane addressing (x4): mi = matrix index group, mrow = row in matrix
    const int mi = lane >> 3, mrow = lane & 7;
    // K/V B-fragments: rows = key/d octets (mi>>1), chunks via cbase = mi&1
    const uint32_t krow = (uint32_t)((8 * (mi >> 1) + mrow) * 256);
    const uint32_t vrow = (uint32_t)((8 * (mi >> 1) + mrow) * VROWB);
    const int cbase = mi & 1;
    // Q A-fragments: rows = (mi&1) half, chunks via qhi = mi>>1
    const uint32_t qrow0 = Qaddr + (uint32_t)((warp * 32 + (mi & 1) * 8 + mrow) * 256);
    const uint32_t qrow1 = qrow0 + 16u * 256u;
    const int qhi = mi >> 1;

    const int rA = warp * 32 + g;

    float oa[2][16][4];
#pragma unroll
    for (int h = 0; h < 2; h++)
#pragma unroll
        for (int n = 0; n < 16; n++)
            oa[h][n][0] = oa[h][n][1] = oa[h][n][2] = oa[h][n][3] = 0.f;
    float l00 = 0.f, l01 = 0.f, l10 = 0.f, l11 = 0.f;

#pragma unroll 1
    for (int t = 0; t < ntiles; t++) {
        const int bi = t & (NSTAGE - 1);
        const int rem = ntiles - 1 - t;
        if (rem >= 2)
            asm volatile("cp.async.wait_group 2;" ::: "memory");
        else if (rem == 1)
            asm volatile("cp.async.wait_group 1;" ::: "memory");
        else
            asm volatile("cp.async.wait_group 0;" ::: "memory");
        __syncthreads();             // tile t visible; all warps done with t-1
        if (t + 3 < ntiles) issue_tile(t + 3, (t + 3) & (NSTAGE - 1));

        const uint32_t kb = Kaddr[bi] + krow;
        const uint32_t vb = Vaddr[bi] + vrow;

        // ---- S = (Q*scale) K^T : Q A-frags via ldmatrix, K B-frags shared
        float sa[2][4][4];
#pragma unroll
        for (int h = 0; h < 2; h++)
#pragma unroll
            for (int j = 0; j < 4; j++)
                sa[h][j][0] = sa[h][j][1] = sa[h][j][2] = sa[h][j][3] = 0.f;
#pragma unroll
        for (int kk = 0; kk < 8; kk++) {
            const uint32_t qoff = (uint32_t)(((kk * 2 + qhi) ^ mrow) << 4);
            uint32_t aq0[4], aq1[4];
            ldsm4(aq0[0], aq0[1], aq0[2], aq0[3], qrow0 + qoff);
            ldsm4(aq1[0], aq1[1], aq1[2], aq1[3], qrow1 + qoff);
            const uint32_t kch = (uint32_t)(((kk * 2 + cbase) ^ mrow) << 4);
#pragma unroll
            for (int jp = 0; jp < 2; jp++) {
                uint32_t t0, t1, t2, t3;
                ldsm4(t0, t1, t2, t3, kb + jp * 4096 + kch);
                mma16(sa[0][2 * jp], aq0[0], aq0[1], aq0[2], aq0[3], t0, t1);
                mma16(sa[0][2 * jp + 1], aq0[0], aq0[1], aq0[2], aq0[3], t2, t3);
                mma16(sa[1][2 * jp], aq1[0], aq1[1], aq1[2], aq1[3], t0, t1);
                mma16(sa[1][2 * jp + 1], aq1[0], aq1[1], aq1[2], aq1[3], t2, t3);
            }
        }

        // ---- p = 2^s (padding rows zero -> p = 1, fixed in epilogue) ----
        uint32_t ph0[2][4], ph1[2][4];
#pragma unroll
        for (int j = 0; j < 4; j++) {
            float a0 = exp2f(sa[0][j][0]);
            float a1 = exp2f(sa[0][j][1]);
            float a2 = exp2f(sa[0][j][2]);
            float a3 = exp2f(sa[0][j][3]);
            l00 += a0 + a1;
            l01 += a2 + a3;
            ph0[0][j] = f2h2(a0, a1);
            ph1[0][j] = f2h2(a2, a3);
            float b0 = exp2f(sa[1][j][0]);
            float b1 = exp2f(sa[1][j][1]);
            float b2 = exp2f(sa[1][j][2]);
            float b3 = exp2f(sa[1][j][3]);
            l10 += b0 + b1;
            l11 += b2 + b3;
            ph0[1][j] = f2h2(b0, b1);
            ph1[1][j] = f2h2(b2, b3);
        }

        // ---- O += P V : each ldsm4 feeds 4 MMAs ----
#pragma unroll
        for (int kh = 0; kh < 2; kh++) {
            const uint32_t vch = (uint32_t)((kh * 2 + cbase) << 4);
            uint32_t a0 = ph0[0][2 * kh], a1 = ph1[0][2 * kh];
            uint32_t a2 = ph0[0][2 * kh + 1], a3 = ph1[0][2 * kh + 1];
            uint32_t b0 = ph0[1][2 * kh], b1 = ph1[1][2 * kh];
            uint32_t b2 = ph0[1][2 * kh + 1], b3 = ph1[1][2 * kh + 1];
#pragma unroll
            for (int np = 0; np < 8; np++) {
                uint32_t t0, t1, t2, t3;
                ldsm4(t0, t1, t2, t3, vb + np * (16 * VROWB) + vch);
                mma16(oa[0][2 * np], a0, a1, a2, a3, t0, t1);
                mma16(oa[0][2 * np + 1], a0, a1, a2, a3, t2, t3);
                mma16(oa[1][2 * np], b0, b1, b2, b3, t0, t1);
                mma16(oa[1][2 * np + 1], b0, b1, b2, b3, t2, t3);
            }
        }
    }

    // ---- epilogue: quad-reduce l, subtract exact padding count, store ----
    l00 += __shfl_xor_sync(0xffffffffu, l00, 1);
    l00 += __shfl_xor_sync(0xffffffffu, l00, 2);
    l01 += __shfl_xor_sync(0xffffffffu, l01, 1);
    l01 += __shfl_xor_sync(0xffffffffu, l01, 2);
    l10 += __shfl_xor_sync(0xffffffffu, l10, 1);
    l10 += __shfl_xor_sync(0xffffffffu, l10, 2);
    l11 += __shfl_xor_sync(0xffffffffu, l11, 1);
    l11 += __shfl_xor_sync(0xffffffffu, l11, 2);
    const float inv[2][2] = {{1.f / (l00 - padf), 1.f / (l01 - padf)},
                             {1.f / (l10 - padf), 1.f / (l11 - padf)}};
    float* og = out + bh_base + (size_t)qb * BM * Dd;
#pragma unroll
    for (int h = 0; h < 2; h++) {
        const int ra = rA + 16 * h, rb = ra + 8;
#pragma unroll
        for (int n = 0; n < 16; n++) {
            int c = n * 8 + 2 * tig;
            *(float2*)(og + (size_t)ra * Dd + c) =
                make_float2(oa[h][n][0] * inv[h][0], oa[h][n][1] * inv[h][0]);
            *(float2*)(og + (size_t)rb * Dd + c) =
                make_float2(oa[h][n][2] * inv[h][1], oa[h][n][3] * inv[h][1]);
        }
    }
}

extern "C" void kernel_launch(void* const* d_in, const int* in_sizes, int n_in,
                              void* d_out, int out_size) {
    (void)in_sizes; (void)n_in; (void)out_size;
    const float* q = (const float*)d_in[0];
    const float* k = (const float*)d_in[1];
    const float* v = (const float*)d_in[2];
    const int* mask = (const int*)d_in[3];
    float* out = (float*)d_out;

    prep_kernel<<<dim3(Ss / 64, Bc * Hh), 256>>>(k, v, mask);

    constexpr int SMEM_BYTES = QTILEB + NSTAGE * (KTILEB + VTILEB);  // 106496
    cudaFuncSetAttribute(fa_kernel, cudaFuncAttributeMaxDynamicSharedMemorySize,
                         SMEM_BYTES);
    fa_kernel<<<dim3(Ss / BM, Bc * Hh), NT, SMEM_BYTES>>>(q, mask, out);
}